// round 16
// baseline (speedup 1.0000x reference)
#include <cuda_runtime.h>
#include <cuda_bf16.h>
#include <math.h>

// ---------------------------------------------------------------------------
// Problem constants
// ---------------------------------------------------------------------------
#define G_      16
#define C_      4
#define R_      64
#define MUL_    128
#define KDIM    36          // (LMAX+1)^2
#define RB      180
#define RA      359
#define NPIX    (RB*RA)     // 64620
#define NPIX4   (NPIX/4)    // 16155
#define EMB     4608
#define NIRR    768
#define MDIM    12          // 11 signed-m slots (m=-5..5) + 1 pad
#define NROWS   8           // beta rows a 2048-pixel tile can span (<=7)
#define TPB     512         // threads per pixel block
#define TILES   32          // tiles per graph (32*512 = 16384 >= 16155)

#define RSQRT_MUL 0.08838834764831845f   // 1/sqrt(128)
#define RSQRT_RAD 0.125f                 // 1/sqrt(64)
#define B0C       0.28209479177387814f   // Y00 = 1/sqrt(4*pi)
#define PI_F      3.14159265358979323846f

// output layout: concat of the 4 returned tensors, flattened, in order
#define OFF_LPC  0
#define OFF_POS  147456                          // 16*4*64*36
#define OFF_ANG  (OFF_POS + 66170880)            // + 16*64*64620
#define OFF_RAD  (OFF_ANG + 1033920)             // + 16*64620

// ---------------------------------------------------------------------------
// Device scratch
// ---------------------------------------------------------------------------
__device__ float g_F[RB][KDIM];      // beta SH factor (norm & sqrt2 included)
__device__ float g_ang[G_*C_*KDIM];  // angular coefficients
__device__ float g_rad[G_*R_];       // radial logits

__device__ __forceinline__ int lofk(int k) {
    const int t[36] = {0,1,1,1,2,2,2,2,2,3,3,3,3,3,3,3,
                       4,4,4,4,4,4,4,4,4,5,5,5,5,5,5,5,5,5,5,5};
    return t[k];
}

// ---------------------------------------------------------------------------
// K_setup: fused k_nodes (blocks 0..RB-1) + k_front (blocks RB..RB+G_-1).
// (Unchanged R4/R15 configuration.)
// ---------------------------------------------------------------------------
__device__ void nodes_body(int b) {
    __shared__ float sca[RB + 1], scb[RB + 1];

    const int n = RB;
    for (int k = 2 + threadIdx.x; k <= n; k += 128) {
        sca[k] = (float)((2.0 * k - 1.0) / (double)k);
        scb[k] = (float)((k - 1.0) / (double)k);
    }
    __syncthreads();
    if (threadIdx.x != 0) return;

    int i = n - 1 - b;   // descending guess index -> ascending y (numpy order)
    float xf = (float)cos((double)PI_F * (i + 0.75) / (n + 0.5));

    #pragma unroll 1
    for (int it = 0; it < 4; it++) {
        float p0 = 1.0f, p1 = xf;
        #pragma unroll 4
        for (int k = 2; k <= n; k++) {
            float p2 = fmaf(sca[k] * xf, p1, -scb[k] * p0);
            p0 = p1; p1 = p2;
        }
        float dp = n * (xf * p1 - p0) / (xf * xf - 1.0f);
        xf -= p1 / dp;
    }

    double y = (double)xf;
    double somx2 = sqrt(fmax(1.0 - y * y, 0.0));
    double P[6][6];
    P[0][0] = 1.0;
    for (int m = 1; m <= 5; m++) P[m][m] = -(2.0 * m - 1.0) * somx2 * P[m-1][m-1];
    for (int m = 0; m < 5; m++)  P[m+1][m] = (2.0 * m + 1.0) * y * P[m][m];
    for (int m = 0; m <= 5; m++)
        for (int l = m + 2; l <= 5; l++)
            P[l][m] = ((2.0*l - 1.0) * y * P[l-1][m] - (l + m - 1.0) * P[l-2][m]) / (double)(l - m);

    double fact[11];
    fact[0] = 1.0;
    for (int q = 1; q <= 10; q++) fact[q] = fact[q-1] * q;

    for (int l = 0; l <= 5; l++) {
        for (int m = 0; m <= l; m++) {
            double N = sqrt((2.0*l + 1.0) / (4.0 * 3.14159265358979323846) * fact[l-m] / fact[l+m]);
            if (m == 0) {
                g_F[b][l*l + l] = (float)(N * P[l][0]);
            } else {
                double v = sqrt(2.0) * N * P[l][m];
                g_F[b][l*l + l + m] = (float)v;  // cos(m*alpha) partner
                g_F[b][l*l + l - m] = (float)v;  // sin(m*alpha) partner
            }
        }
    }
}

__device__ void front_body(int g,
                           const float* __restrict__ emb,
                           const float* __restrict__ spec,
                           const float* __restrict__ Wr,
                           const float* __restrict__ Wm1,
                           const float* __restrict__ Wm2,
                           const float* const* Wa,
                           const int* __restrict__ focus,
                           const int* __restrict__ tspec,
                           float* __restrict__ out) {
    __shared__ float s_sc[KDIM][MUL_ + 1];
    __shared__ float s_r[64];
    __shared__ float s_h[128];
    __shared__ float s_rad[64];

    int u = threadIdx.x;
    const float* f  = emb  + (size_t)focus[g] * EMB;
    const float* sp = spec + (size_t)tspec[g] * NIRR;

    #pragma unroll
    for (int l = 0; l <= 5; l++) {
        float s = sp[128*l + u];
        int d = 2*l + 1;
        const float* fb = f + 128*l*l + u*d;
        for (int m = 0; m < d; m++) s_sc[l*l + m][u] = fb[m] * s;
    }
    __syncthreads();

    if (u < 64) {
        float acc = 0.f;
        #pragma unroll 8
        for (int v = 0; v < 128; v++) acc += s_sc[0][v] * Wr[v*64 + u];
        s_r[u] = acc * RSQRT_MUL;
    }
    __syncthreads();

    {
        float acc = 0.f;
        #pragma unroll 8
        for (int j = 0; j < 64; j++) acc += s_r[j] * Wm1[j*128 + u];
        acc *= RSQRT_RAD;
        s_h[u] = fmaxf(acc, 0.f) + log1pf(expf(-fabsf(acc)));
    }
    __syncthreads();

    if (u < 64) {
        float acc = 0.f;
        #pragma unroll 8
        for (int v = 0; v < 128; v++) acc += s_h[v] * Wm2[v*64 + u];
        acc *= RSQRT_MUL;
        s_rad[u] = acc;
        g_rad[g*64 + u] = acc;
        out[OFF_RAD + g*64 + u] = acc;
    }
    __syncthreads();

    for (int o = u; o < C_*KDIM; o += 128) {
        int k = o >> 2, c = o & 3;
        int l = lofk(k);
        const float* w = Wa[l];
        float acc = 0.f;
        #pragma unroll 8
        for (int v = 0; v < 128; v++) acc += s_sc[k][v] * w[v*4 + c];
        acc *= RSQRT_MUL;
        g_ang[(g*C_ + c)*KDIM + k] = acc;

        float* lp = out + OFF_LPC + ((size_t)(g*C_ + c) * R_) * KDIM + k;
        if (k == 0) {
            #pragma unroll 8
            for (int r = 0; r < 64; r++) lp[r*KDIM] = acc + s_rad[r];
        } else {
            #pragma unroll 8
            for (int r = 0; r < 64; r++) lp[r*KDIM] = acc;
        }
    }
}

__global__ void __launch_bounds__(128) k_setup(
        const float* __restrict__ emb, const float* __restrict__ spec,
        const float* __restrict__ Wr, const float* __restrict__ Wm1,
        const float* __restrict__ Wm2,
        const float* __restrict__ Wa0, const float* __restrict__ Wa1,
        const float* __restrict__ Wa2, const float* __restrict__ Wa3,
        const float* __restrict__ Wa4, const float* __restrict__ Wa5,
        const int* __restrict__ focus, const int* __restrict__ tspec,
        float* __restrict__ out) {
    if (blockIdx.x < RB) {
        nodes_body(blockIdx.x);
    } else {
        const float* Wa[6] = {Wa0, Wa1, Wa2, Wa3, Wa4, Wa5};
        front_body(blockIdx.x - RB, emb, spec, Wr, Wm1, Wm2, Wa, focus, tspec, out);
    }
}

// ---------------------------------------------------------------------------
// K_grid: R15 store logic with 512-thread blocks at 1 block/SM:
//   - 148 concurrent write streams (was 296)
//   - 8KB contiguous run per r-plane visit (was 4KB)
// Same warps/SM (16) as R15, so issue capacity unchanged.
// grid = (TILES=32, 16).
// ---------------------------------------------------------------------------
__global__ void __launch_bounds__(TPB, 1) k_grid(float* __restrict__ out) {
    __shared__ __align__(16) float s_A[NROWS][C_][MDIM];  // m-separated coeffs
    __shared__ float s_radB[R_];

    int g  = blockIdx.y;
    int p0 = blockIdx.x * TPB;            // first 4-pixel group of this block
    int b0 = (4 * p0) / RA;               // first beta row touched

    if (threadIdx.x < R_) s_radB[threadIdx.x] = g_rad[g*R_ + threadIdx.x] * B0C;

    if (threadIdx.x < NROWS * C_ * MDIM) {
        int j   = threadIdx.x % MDIM;
        int c   = (threadIdx.x / MDIM) & 3;
        int row = threadIdx.x / (MDIM * C_);
        int b   = b0 + row;
        float acc = 0.f;
        if (j < 11 && b < RB) {
            int ms = j - 5;
            int am = ms < 0 ? -ms : ms;
            const float* ag = &g_ang[(g*C_ + c) * KDIM];
            #pragma unroll 1
            for (int l = am; l <= 5; l++) {
                int k = l*l + l + ms;
                acc += ag[k] * g_F[b][k];
            }
        }
        s_A[row][c][j] = acc;
    }
    __syncthreads();

    int p = p0 + threadIdx.x;
    if (p >= NPIX4) return;

    const float4* A4 = (const float4*)&s_A[0][0][0];

    float lse4[4];
    #pragma unroll
    for (int s = 0; s < 4; s++) {
        int pix = 4*p + s;
        int b = pix / RA;
        int a = pix - b * RA;
        int row = b - b0;

        float c1, s1;
        float al = (float)((2.0 * 3.14159265358979323846 / (double)RA) * (double)a);
        __sincosf(al, &s1, &c1);
        float c2x = 2.f * c1;
        float cm2 = c2x*c1 - 1.f,  sm2 = c2x*s1;
        float cm3 = c2x*cm2 - c1,  sm3 = c2x*sm2 - s1;
        float cm4 = c2x*cm3 - cm2, sm4 = c2x*sm3 - sm2;
        float cm5 = c2x*cm4 - cm3, sm5 = c2x*sm4 - sm3;
        float t0 = sm5, t1 = sm4, t2 = sm3, t3 = sm2, t4 = s1;
        float t5 = 1.f, t6 = c1, t7 = cm2, t8 = cm3, t9 = cm4, t10 = cm5;

        float v[4];
        #pragma unroll
        for (int c = 0; c < 4; c++) {
            float4 a0 = A4[(row*4 + c)*3 + 0];
            float4 a1 = A4[(row*4 + c)*3 + 1];
            float4 a2 = A4[(row*4 + c)*3 + 2];
            float acc;
            acc = a0.x * t0;
            acc = fmaf(a0.y, t1, acc);
            acc = fmaf(a0.z, t2, acc);
            acc = fmaf(a0.w, t3, acc);
            acc = fmaf(a1.x, t4, acc);
            acc = fmaf(a1.y, t5, acc);
            acc = fmaf(a1.z, t6, acc);
            acc = fmaf(a1.w, t7, acc);
            acc = fmaf(a2.x, t8, acc);
            acc = fmaf(a2.y, t9, acc);
            acc = fmaf(a2.z, t10, acc);
            v[c] = acc;
        }
        float mx = fmaxf(fmaxf(v[0], v[1]), fmaxf(v[2], v[3]));
        lse4[s] = mx + __logf(__expf(v[0]-mx) + __expf(v[1]-mx)
                            + __expf(v[2]-mx) + __expf(v[3]-mx));
    }

    float4 L = make_float4(lse4[0], lse4[1], lse4[2], lse4[3]);
    __stcs((float4*)(out + OFF_ANG + (size_t)g * NPIX + 4*p), L);

    float* pp = out + OFF_POS + ((size_t)g * R_) * NPIX + 4*p;
    #pragma unroll 8
    for (int r = 0; r < R_; r++) {
        float rb = s_radB[r];
        __stcs((float4*)pp, make_float4(L.x + rb, L.y + rb, L.z + rb, L.w + rb));
        pp += NPIX;
    }
}

// ---------------------------------------------------------------------------
extern "C" void kernel_launch(void* const* d_in, const int* in_sizes, int n_in,
                              void* d_out, int out_size) {
    const float* emb  = (const float*)d_in[0];
    const float* spec = (const float*)d_in[1];
    const float* Wr   = (const float*)d_in[2];
    const float* Wm1  = (const float*)d_in[3];
    const float* Wm2  = (const float*)d_in[4];
    const float* Wa0  = (const float*)d_in[5];
    const float* Wa1  = (const float*)d_in[6];
    const float* Wa2  = (const float*)d_in[7];
    const float* Wa3  = (const float*)d_in[8];
    const float* Wa4  = (const float*)d_in[9];
    const float* Wa5  = (const float*)d_in[10];
    const int* focus  = (const int*)d_in[11];
    const int* tspec  = (const int*)d_in[12];
    float* out = (float*)d_out;

    k_setup<<<RB + G_, 128>>>(emb, spec, Wr, Wm1, Wm2,
                              Wa0, Wa1, Wa2, Wa3, Wa4, Wa5,
                              focus, tspec, out);
    dim3 gg(TILES, G_);
    k_grid<<<gg, TPB>>>(out);
}

// round 17
// speedup vs baseline: 1.1000x; 1.1000x over previous
#include <cuda_runtime.h>
#include <cuda_bf16.h>
#include <math.h>

// ---------------------------------------------------------------------------
// Problem constants
// ---------------------------------------------------------------------------
#define G_      16
#define C_      4
#define R_      64
#define MUL_    128
#define KDIM    36          // (LMAX+1)^2
#define RB      180
#define RA      359
#define NPIX    (RB*RA)     // 64620
#define NPIX4   (NPIX/4)    // 16155
#define EMB     4608
#define NIRR    768
#define MDIM    12          // 11 signed-m slots (m=-5..5) + 1 pad

#define RSQRT_MUL 0.08838834764831845f   // 1/sqrt(128)
#define RSQRT_RAD 0.125f                 // 1/sqrt(64)
#define B0C       0.28209479177387814f   // Y00 = 1/sqrt(4*pi)
#define PI_F      3.14159265358979323846f

// output layout: concat of the 4 returned tensors, flattened, in order
#define OFF_LPC  0
#define OFF_POS  147456                          // 16*4*64*36
#define OFF_ANG  (OFF_POS + 66170880)            // + 16*64*64620
#define OFF_RAD  (OFF_ANG + 1033920)             // + 16*64620

// ---------------------------------------------------------------------------
// Device scratch
// ---------------------------------------------------------------------------
__device__ float g_F[RB][KDIM];      // beta SH factor (norm & sqrt2 included)
__device__ float g_ang[G_*C_*KDIM];  // angular coefficients
__device__ float g_rad[G_*R_];       // radial logits

__device__ __forceinline__ int lofk(int k) {
    const int t[36] = {0,1,1,1,2,2,2,2,2,3,3,3,3,3,3,3,
                       4,4,4,4,4,4,4,4,4,5,5,5,5,5,5,5,5,5,5,5};
    return t[k];
}

// ---------------------------------------------------------------------------
// K_setup: fused k_nodes (blocks 0..RB-1) + k_front (blocks RB..RB+G_-1).
// (Unchanged R4/R15 configuration.)
// ---------------------------------------------------------------------------
__device__ void nodes_body(int b) {
    __shared__ float sca[RB + 1], scb[RB + 1];

    const int n = RB;
    for (int k = 2 + threadIdx.x; k <= n; k += 128) {
        sca[k] = (float)((2.0 * k - 1.0) / (double)k);
        scb[k] = (float)((k - 1.0) / (double)k);
    }
    __syncthreads();
    if (threadIdx.x != 0) return;

    int i = n - 1 - b;   // descending guess index -> ascending y (numpy order)
    float xf = (float)cos((double)PI_F * (i + 0.75) / (n + 0.5));

    #pragma unroll 1
    for (int it = 0; it < 4; it++) {
        float p0 = 1.0f, p1 = xf;
        #pragma unroll 4
        for (int k = 2; k <= n; k++) {
            float p2 = fmaf(sca[k] * xf, p1, -scb[k] * p0);
            p0 = p1; p1 = p2;
        }
        float dp = n * (xf * p1 - p0) / (xf * xf - 1.0f);
        xf -= p1 / dp;
    }

    double y = (double)xf;
    double somx2 = sqrt(fmax(1.0 - y * y, 0.0));
    double P[6][6];
    P[0][0] = 1.0;
    for (int m = 1; m <= 5; m++) P[m][m] = -(2.0 * m - 1.0) * somx2 * P[m-1][m-1];
    for (int m = 0; m < 5; m++)  P[m+1][m] = (2.0 * m + 1.0) * y * P[m][m];
    for (int m = 0; m <= 5; m++)
        for (int l = m + 2; l <= 5; l++)
            P[l][m] = ((2.0*l - 1.0) * y * P[l-1][m] - (l + m - 1.0) * P[l-2][m]) / (double)(l - m);

    double fact[11];
    fact[0] = 1.0;
    for (int q = 1; q <= 10; q++) fact[q] = fact[q-1] * q;

    for (int l = 0; l <= 5; l++) {
        for (int m = 0; m <= l; m++) {
            double N = sqrt((2.0*l + 1.0) / (4.0 * 3.14159265358979323846) * fact[l-m] / fact[l+m]);
            if (m == 0) {
                g_F[b][l*l + l] = (float)(N * P[l][0]);
            } else {
                double v = sqrt(2.0) * N * P[l][m];
                g_F[b][l*l + l + m] = (float)v;  // cos(m*alpha) partner
                g_F[b][l*l + l - m] = (float)v;  // sin(m*alpha) partner
            }
        }
    }
}

__device__ void front_body(int g,
                           const float* __restrict__ emb,
                           const float* __restrict__ spec,
                           const float* __restrict__ Wr,
                           const float* __restrict__ Wm1,
                           const float* __restrict__ Wm2,
                           const float* const* Wa,
                           const int* __restrict__ focus,
                           const int* __restrict__ tspec,
                           float* __restrict__ out) {
    __shared__ float s_sc[KDIM][MUL_ + 1];
    __shared__ float s_r[64];
    __shared__ float s_h[128];
    __shared__ float s_rad[64];

    int u = threadIdx.x;
    const float* f  = emb  + (size_t)focus[g] * EMB;
    const float* sp = spec + (size_t)tspec[g] * NIRR;

    #pragma unroll
    for (int l = 0; l <= 5; l++) {
        float s = sp[128*l + u];
        int d = 2*l + 1;
        const float* fb = f + 128*l*l + u*d;
        for (int m = 0; m < d; m++) s_sc[l*l + m][u] = fb[m] * s;
    }
    __syncthreads();

    if (u < 64) {
        float acc = 0.f;
        #pragma unroll 8
        for (int v = 0; v < 128; v++) acc += s_sc[0][v] * Wr[v*64 + u];
        s_r[u] = acc * RSQRT_MUL;
    }
    __syncthreads();

    {
        float acc = 0.f;
        #pragma unroll 8
        for (int j = 0; j < 64; j++) acc += s_r[j] * Wm1[j*128 + u];
        acc *= RSQRT_RAD;
        s_h[u] = fmaxf(acc, 0.f) + log1pf(expf(-fabsf(acc)));
    }
    __syncthreads();

    if (u < 64) {
        float acc = 0.f;
        #pragma unroll 8
        for (int v = 0; v < 128; v++) acc += s_h[v] * Wm2[v*64 + u];
        acc *= RSQRT_MUL;
        s_rad[u] = acc;
        g_rad[g*64 + u] = acc;
        out[OFF_RAD + g*64 + u] = acc;
    }
    __syncthreads();

    for (int o = u; o < C_*KDIM; o += 128) {
        int k = o >> 2, c = o & 3;
        int l = lofk(k);
        const float* w = Wa[l];
        float acc = 0.f;
        #pragma unroll 8
        for (int v = 0; v < 128; v++) acc += s_sc[k][v] * w[v*4 + c];
        acc *= RSQRT_MUL;
        g_ang[(g*C_ + c)*KDIM + k] = acc;

        float* lp = out + OFF_LPC + ((size_t)(g*C_ + c) * R_) * KDIM + k;
        if (k == 0) {
            #pragma unroll 8
            for (int r = 0; r < 64; r++) lp[r*KDIM] = acc + s_rad[r];
        } else {
            #pragma unroll 8
            for (int r = 0; r < 64; r++) lp[r*KDIM] = acc;
        }
    }
}

__global__ void __launch_bounds__(128) k_setup(
        const float* __restrict__ emb, const float* __restrict__ spec,
        const float* __restrict__ Wr, const float* __restrict__ Wm1,
        const float* __restrict__ Wm2,
        const float* __restrict__ Wa0, const float* __restrict__ Wa1,
        const float* __restrict__ Wa2, const float* __restrict__ Wa3,
        const float* __restrict__ Wa4, const float* __restrict__ Wa5,
        const int* __restrict__ focus, const int* __restrict__ tspec,
        float* __restrict__ out) {
    if (blockIdx.x < RB) {
        nodes_body(blockIdx.x);
    } else {
        const float* Wa[6] = {Wa0, Wa1, Wa2, Wa3, Wa4, Wa5};
        front_body(blockIdx.x - RB, emb, spec, Wr, Wm1, Wm2, Wa, focus, tspec, out);
    }
}

// ---------------------------------------------------------------------------
// K_grid: byte-identical R15 body (256 threads, 4-pixel groups, float4
// streaming stores) with residency capped at 1 block/SM: 148 concurrent
// write streams (R15: 296). Isolates the stream-count variable that R16
// confounded with block width.
// ---------------------------------------------------------------------------
__global__ void __launch_bounds__(256, 1) k_grid(float* __restrict__ out) {
    __shared__ __align__(16) float s_A[4][C_][MDIM];  // m-separated coeffs
    __shared__ float s_radB[R_];

    int g  = blockIdx.y;
    int p0 = blockIdx.x * 256;            // first 4-pixel group of this block
    int b0 = (4 * p0) / RA;               // first beta row touched

    if (threadIdx.x < R_) s_radB[threadIdx.x] = g_rad[g*R_ + threadIdx.x] * B0C;

    if (threadIdx.x < 4 * C_ * MDIM) {
        int j   = threadIdx.x % MDIM;
        int c   = (threadIdx.x / MDIM) & 3;
        int row = threadIdx.x / (MDIM * C_);
        int b   = b0 + row;
        float acc = 0.f;
        if (j < 11 && b < RB) {
            int ms = j - 5;
            int am = ms < 0 ? -ms : ms;
            const float* ag = &g_ang[(g*C_ + c) * KDIM];
            #pragma unroll 1
            for (int l = am; l <= 5; l++) {
                int k = l*l + l + ms;
                acc += ag[k] * g_F[b][k];
            }
        }
        s_A[row][c][j] = acc;
    }
    __syncthreads();

    int p = p0 + threadIdx.x;
    if (p >= NPIX4) return;

    const float4* A4 = (const float4*)&s_A[0][0][0];

    float lse4[4];
    #pragma unroll
    for (int s = 0; s < 4; s++) {
        int pix = 4*p + s;
        int b = pix / RA;
        int a = pix - b * RA;
        int row = b - b0;

        float c1, s1;
        float al = (float)((2.0 * 3.14159265358979323846 / (double)RA) * (double)a);
        __sincosf(al, &s1, &c1);
        float c2x = 2.f * c1;
        float cm2 = c2x*c1 - 1.f,  sm2 = c2x*s1;
        float cm3 = c2x*cm2 - c1,  sm3 = c2x*sm2 - s1;
        float cm4 = c2x*cm3 - cm2, sm4 = c2x*sm3 - sm2;
        float cm5 = c2x*cm4 - cm3, sm5 = c2x*sm4 - sm3;
        float t0 = sm5, t1 = sm4, t2 = sm3, t3 = sm2, t4 = s1;
        float t5 = 1.f, t6 = c1, t7 = cm2, t8 = cm3, t9 = cm4, t10 = cm5;

        float v[4];
        #pragma unroll
        for (int c = 0; c < 4; c++) {
            float4 a0 = A4[(row*4 + c)*3 + 0];
            float4 a1 = A4[(row*4 + c)*3 + 1];
            float4 a2 = A4[(row*4 + c)*3 + 2];
            float acc;
            acc = a0.x * t0;
            acc = fmaf(a0.y, t1, acc);
            acc = fmaf(a0.z, t2, acc);
            acc = fmaf(a0.w, t3, acc);
            acc = fmaf(a1.x, t4, acc);
            acc = fmaf(a1.y, t5, acc);
            acc = fmaf(a1.z, t6, acc);
            acc = fmaf(a1.w, t7, acc);
            acc = fmaf(a2.x, t8, acc);
            acc = fmaf(a2.y, t9, acc);
            acc = fmaf(a2.z, t10, acc);
            v[c] = acc;
        }
        float mx = fmaxf(fmaxf(v[0], v[1]), fmaxf(v[2], v[3]));
        lse4[s] = mx + __logf(__expf(v[0]-mx) + __expf(v[1]-mx)
                            + __expf(v[2]-mx) + __expf(v[3]-mx));
    }

    float4 L = make_float4(lse4[0], lse4[1], lse4[2], lse4[3]);
    __stcs((float4*)(out + OFF_ANG + (size_t)g * NPIX + 4*p), L);

    float* pp = out + OFF_POS + ((size_t)g * R_) * NPIX + 4*p;
    #pragma unroll 8
    for (int r = 0; r < R_; r++) {
        float rb = s_radB[r];
        __stcs((float4*)pp, make_float4(L.x + rb, L.y + rb, L.z + rb, L.w + rb));
        pp += NPIX;
    }
}

// ---------------------------------------------------------------------------
extern "C" void kernel_launch(void* const* d_in, const int* in_sizes, int n_in,
                              void* d_out, int out_size) {
    const float* emb  = (const float*)d_in[0];
    const float* spec = (const float*)d_in[1];
    const float* Wr   = (const float*)d_in[2];
    const float* Wm1  = (const float*)d_in[3];
    const float* Wm2  = (const float*)d_in[4];
    const float* Wa0  = (const float*)d_in[5];
    const float* Wa1  = (const float*)d_in[6];
    const float* Wa2  = (const float*)d_in[7];
    const float* Wa3  = (const float*)d_in[8];
    const float* Wa4  = (const float*)d_in[9];
    const float* Wa5  = (const float*)d_in[10];
    const int* focus  = (const int*)d_in[11];
    const int* tspec  = (const int*)d_in[12];
    float* out = (float*)d_out;

    k_setup<<<RB + G_, 128>>>(emb, spec, Wr, Wm1, Wm2,
                              Wa0, Wa1, Wa2, Wa3, Wa4, Wa5,
                              focus, tspec, out);
    dim3 gg((NPIX4 + 255) / 256, G_);
    k_grid<<<gg, 256>>>(out);
}